// round 5
// baseline (speedup 1.0000x reference)
#include <cuda_runtime.h>
#include <cstdint>

#define Bdim 2
#define Tdim 1024
#define Edim 1024
#define Hdim 16
#define Ddim 64
#define Rdim 32
#define Mdim (Bdim*Tdim)
#define CH 16

typedef unsigned long long ull;

__device__ float g_diff[(size_t)Mdim*Edim];
__device__ float g_z   [(size_t)Mdim*Edim];
__device__ float g_hdn [(size_t)Mdim*6*Rdim];
__device__ float g_dd  [(size_t)Mdim*6*Edim];
__device__ float g_proj[(size_t)Mdim*5*Edim];
__device__ float g_gate[(size_t)Mdim*Edim];
__device__ float g_wdec[(size_t)Mdim*Edim];
__device__ float g_vr  [(size_t)Mdim*Hdim];
__device__ float g_rwkv[(size_t)Mdim*Edim];
__device__ float g_a   [(size_t)Mdim*Edim];

__device__ __forceinline__ ull pack2(float lo, float hi){
    ull r; asm("mov.b64 %0, {%1, %2};" : "=l"(r) : "f"(lo), "f"(hi)); return r;
}
__device__ __forceinline__ void fma2(ull& d, ull a, ull b){
    asm("fma.rn.f32x2 %0, %1, %2, %3;" : "=l"(d) : "l"(a), "l"(b), "l"(d));
}
__device__ __forceinline__ float2 unpack2(ull v){
    float lo, hi; asm("mov.b64 {%0, %1}, %2;" : "=f"(lo), "=f"(hi) : "l"(v));
    return make_float2(lo, hi);
}

// K1: token shift -> diff, z
__global__ __launch_bounds__(256) void k_shift(const float* __restrict__ x,
                                               const float* __restrict__ mu_x){
    int idx = blockIdx.x*256 + threadIdx.x;
    int e = idx & (Edim-1);
    int m = idx >> 10;
    int t = m & (Tdim-1);
    float xv = x[idx];
    float lx = (t==0) ? 0.f : x[idx - Edim];
    float d  = lx - xv;
    float mt = xv + d*mu_x[e];
    g_diff[idx] = d;
    g_z[idx]    = xv + d*mt;
}

// K2: hdn = tanh(z @ Aw[g] + Ab[g])
__global__ __launch_bounds__(256) void k_loraA(const float* __restrict__ Aw,
                                               const float* __restrict__ Ab){
    __shared__ float zsm[64][36];
    __shared__ float wsm[32][32];
    int g  = blockIdx.y;
    int m0 = blockIdx.x*64;
    int tid = threadIdx.x;
    int n = tid & 31, ty = tid >> 5;
    float acc[8];
    #pragma unroll
    for (int i=0;i<8;i++) acc[i]=0.f;
    const float* wbase = Aw + (size_t)g*Edim*Rdim;
    for (int k0=0;k0<Edim;k0+=32){
        #pragma unroll
        for (int j=0;j<2;j++){
            int f = tid + j*256;
            int row = f>>3, c4 = (f&7)*4;
            *(float4*)&zsm[row][c4] = *(const float4*)&g_z[(size_t)(m0+row)*Edim + k0 + c4];
        }
        {
            int kk = tid>>3, c4 = (tid&7)*4;
            *(float4*)&wsm[kk][c4] = *(const float4*)&wbase[(size_t)(k0+kk)*Rdim + c4];
        }
        __syncthreads();
        #pragma unroll
        for (int kk=0;kk<32;kk++){
            float bw = wsm[kk][n];
            #pragma unroll
            for (int i=0;i<8;i++) acc[i] += zsm[ty*8+i][kk]*bw;
        }
        __syncthreads();
    }
    float bias = Ab[g*Rdim + n];
    #pragma unroll
    for (int i=0;i<8;i++)
        g_hdn[(size_t)(m0+ty*8+i)*192 + g*32 + n] = tanhf(acc[i] + bias);
}

// K3: dd = x + diff*(lam + hdn@Bw + Bb)
__global__ __launch_bounds__(256) void k_loraB(const float* __restrict__ x,
                                               const float* __restrict__ Bw,
                                               const float* __restrict__ lam,
                                               const float* __restrict__ Bb){
    __shared__ float hsm[16][32];
    int g  = blockIdx.z;
    int m0 = blockIdx.y*16;
    int tid = threadIdx.x;
    int e  = blockIdx.x*256 + tid;
    float wreg[32];
    const float* wb = Bw + (size_t)g*Rdim*Edim + e;
    #pragma unroll
    for (int r=0;r<32;r++) wreg[r] = wb[(size_t)r*Edim];
    {
        int f = tid;     hsm[f>>5][f&31] = g_hdn[(size_t)(m0+(f>>5))*192 + g*32 + (f&31)];
        f = tid + 256;   hsm[f>>5][f&31] = g_hdn[(size_t)(m0+(f>>5))*192 + g*32 + (f&31)];
    }
    __syncthreads();
    float base = lam[g*Edim + e] + Bb[g*Edim + e];
    #pragma unroll
    for (int mm=0;mm<16;mm++){
        float acc = base;
        #pragma unroll
        for (int r=0;r<32;r++) acc += hsm[mm][r]*wreg[r];
        int m = m0 + mm;
        size_t xi = (size_t)m*Edim + e;
        g_dd[((size_t)m*6 + g)*Edim + e] = x[xi] + g_diff[xi]*acc;
    }
}

// K4: per-head 64x64 GEMM (R2 proven form, static smem).
__global__ __launch_bounds__(256) void k_headgemm(const float* __restrict__ in, int in_rstride,
                                                  const float* __restrict__ w,
                                                  float* __restrict__ out, int out_rstride){
    __shared__ float ysm[64][68];
    __shared__ float wsm[64][64];
    int unit = blockIdx.y;
    int m0   = blockIdx.x*64;
    int colbase = (unit>>4)*Edim + (unit&15)*64;
    const float* wb = w + (size_t)unit*4096;
    int tid = threadIdx.x;
    #pragma unroll
    for (int j=0;j<4;j++){
        int f = tid + j*256;
        int row = f>>4, c4 = (f&15)*4;
        *(float4*)&ysm[row][c4] = *(const float4*)&in[(size_t)(m0+row)*in_rstride + colbase + c4];
        *(float4*)&wsm[row][c4] = *(const float4*)&wb[row*64 + c4];
    }
    __syncthreads();
    int tx = tid&15, ty = tid>>4;
    int n0 = tx*4, m0r = ty*4;
    ull acc[4][2];
    #pragma unroll
    for (int i=0;i<4;i++){ acc[i][0]=0ull; acc[i][1]=0ull; }
    #pragma unroll 16
    for (int k=0;k<64;k++){
        ull b01 = *(const ull*)&wsm[k][n0];
        ull b23 = *(const ull*)&wsm[k][n0+2];
        #pragma unroll
        for (int i=0;i<4;i++){
            float a = ysm[m0r+i][k];
            ull a2 = pack2(a, a);
            fma2(acc[i][0], a2, b01);
            fma2(acc[i][1], a2, b23);
        }
    }
    #pragma unroll
    for (int i=0;i<4;i++){
        float2 lo = unpack2(acc[i][0]), hi = unpack2(acc[i][1]);
        *(float4*)&out[(size_t)(m0+m0r+i)*out_rstride + colbase + n0] =
            make_float4(lo.x, lo.y, hi.x, hi.y);
    }
}

// K4b: fused decay lora: wdec = exp(-exp(wlam + tanh(w@wA)@wB)), per head.
__global__ __launch_bounds__(256) void k_wdecay(const float* __restrict__ wlam,
                                                const float* __restrict__ wA,
                                                const float* __restrict__ wB){
    __shared__ float asm_[64][68];
    __shared__ float wsm[64][68];
    int h = blockIdx.y;
    int m0 = blockIdx.x*64;
    int tid = threadIdx.x;
    #pragma unroll
    for (int j=0;j<4;j++){
        int f = tid + j*256;
        int row = f>>4, c4 = (f&15)*4;
        *(float4*)&asm_[row][c4] =
            *(const float4*)&g_proj[(size_t)(m0+row)*5*Edim + 3*Edim + h*64 + c4];
        *(float4*)&wsm[row][c4] = *(const float4*)&wA[(size_t)h*4096 + row*64 + c4];
    }
    __syncthreads();
    int tx = tid&15, ty = tid>>4;
    int n0 = tx*4, m0r = ty*4;
    ull acc[4][2];
    #pragma unroll
    for (int i=0;i<4;i++){ acc[i][0]=0ull; acc[i][1]=0ull; }
    #pragma unroll 16
    for (int k=0;k<64;k++){
        ull b01 = *(const ull*)&wsm[k][n0];
        ull b23 = *(const ull*)&wsm[k][n0+2];
        #pragma unroll
        for (int i=0;i<4;i++){
            float a = asm_[m0r+i][k];
            ull a2 = pack2(a, a);
            fma2(acc[i][0], a2, b01);
            fma2(acc[i][1], a2, b23);
        }
    }
    __syncthreads();
    // write tanh(result) back into asm_, reload wsm with wB
    #pragma unroll
    for (int i=0;i<4;i++){
        float2 lo = unpack2(acc[i][0]), hi = unpack2(acc[i][1]);
        *(float4*)&asm_[m0r+i][n0] =
            make_float4(tanhf(lo.x), tanhf(lo.y), tanhf(hi.x), tanhf(hi.y));
        acc[i][0]=0ull; acc[i][1]=0ull;
    }
    #pragma unroll
    for (int j=0;j<4;j++){
        int f = tid + j*256;
        int row = f>>4, c4 = (f&15)*4;
        *(float4*)&wsm[row][c4] = *(const float4*)&wB[(size_t)h*4096 + row*64 + c4];
    }
    __syncthreads();
    #pragma unroll 16
    for (int k=0;k<64;k++){
        ull b01 = *(const ull*)&wsm[k][n0];
        ull b23 = *(const ull*)&wsm[k][n0+2];
        #pragma unroll
        for (int i=0;i<4;i++){
            float a = asm_[m0r+i][k];
            ull a2 = pack2(a, a);
            fma2(acc[i][0], a2, b01);
            fma2(acc[i][1], a2, b23);
        }
    }
    #pragma unroll
    for (int i=0;i<4;i++){
        float2 lo = unpack2(acc[i][0]), hi = unpack2(acc[i][1]);
        float v[4] = {lo.x, lo.y, hi.x, hi.y};
        #pragma unroll
        for (int j=0;j<4;j++)
            v[j] = expf(-expf(v[j] + wlam[h*64 + n0 + j]));
        *(float4*)&g_wdec[(size_t)(m0+m0r+i)*Edim + h*64 + n0] =
            make_float4(v[0],v[1],v[2],v[3]);
    }
}

// K5: C[M,1024] = A @ W (+bias). 128x128 tile, 256 thr, 8x8/thread, dup-A f32x2,
// zero pack MOVs (ulonglong2 loads of adjacent pairs).
__global__ __launch_bounds__(256) void k_gemm(const float* __restrict__ A, int arstride,
                                              const float* __restrict__ W,
                                              const float* __restrict__ bias,
                                              float* __restrict__ C, int crstride){
    __shared__ float As2[128][20];   // dup pairs for 8 k (16 floats) + pad
    __shared__ float Bs[8][132];
    int tid = threadIdx.x;
    int mBase = blockIdx.x*128, nBase = blockIdx.y*128;
    int tx = tid&15, ty = tid>>4;
    int n0 = tx*8, m0r = ty*8;
    int arow = tid>>1, ks = (tid&1)*4;
    int brow = tid>>5, bc4 = (tid&31)*4;
    const float* aptr = A + (size_t)(mBase+arow)*arstride + ks;
    const float* bptr = W + (size_t)brow*Edim + nBase + bc4;
    ull acc[8][4];
    #pragma unroll
    for (int i=0;i<8;i++){ acc[i][0]=0; acc[i][1]=0; acc[i][2]=0; acc[i][3]=0; }
    float4 av = *(const float4*)(aptr);
    float4 bv = *(const float4*)(bptr);
    for (int k0=0;k0<Edim;k0+=8){
        *(float4*)&As2[arow][2*ks]   = make_float4(av.x,av.x,av.y,av.y);
        *(float4*)&As2[arow][2*ks+4] = make_float4(av.z,av.z,av.w,av.w);
        *(float4*)&Bs[brow][bc4] = bv;
        __syncthreads();
        if (k0+8 < Edim){
            av = *(const float4*)(aptr + k0 + 8);
            bv = *(const float4*)(bptr + (size_t)(k0+8)*Edim);
        }
        #pragma unroll
        for (int k2=0;k2<4;k2++){
            ulonglong2 b0  = *(const ulonglong2*)&Bs[2*k2][n0];
            ulonglong2 b0b = *(const ulonglong2*)&Bs[2*k2][n0+4];
            ulonglong2 b1  = *(const ulonglong2*)&Bs[2*k2+1][n0];
            ulonglong2 b1b = *(const ulonglong2*)&Bs[2*k2+1][n0+4];
            #pragma unroll
            for (int i=0;i<8;i++){
                ulonglong2 aa = *(const ulonglong2*)&As2[m0r+i][4*k2];
                fma2(acc[i][0], aa.x, b0.x);
                fma2(acc[i][1], aa.x, b0.y);
                fma2(acc[i][2], aa.x, b0b.x);
                fma2(acc[i][3], aa.x, b0b.y);
                fma2(acc[i][0], aa.y, b1.x);
                fma2(acc[i][1], aa.y, b1.y);
                fma2(acc[i][2], aa.y, b1b.x);
                fma2(acc[i][3], aa.y, b1b.y);
            }
        }
        __syncthreads();
    }
    #pragma unroll
    for (int i=0;i<8;i++){
        float2 p0 = unpack2(acc[i][0]), p1 = unpack2(acc[i][1]);
        float2 p2 = unpack2(acc[i][2]), p3 = unpack2(acc[i][3]);
        float4 o0 = make_float4(p0.x,p0.y,p1.x,p1.y);
        float4 o1 = make_float4(p2.x,p2.y,p3.x,p3.y);
        if (bias){
            o0.x += bias[nBase+n0+0]; o0.y += bias[nBase+n0+1];
            o0.z += bias[nBase+n0+2]; o0.w += bias[nBase+n0+3];
            o1.x += bias[nBase+n0+4]; o1.y += bias[nBase+n0+5];
            o1.z += bias[nBase+n0+6]; o1.w += bias[nBase+n0+7];
        }
        float* crow = &C[(size_t)(mBase+m0r+i)*crstride + nBase + n0];
        *(float4*)crow = o0;
        *(float4*)(crow+4) = o1;
    }
}

// K6: vr[m,h] = dot(v,r)
__global__ __launch_bounds__(256) void k_vr(){
    int unit = blockIdx.x*8 + (threadIdx.x>>5);
    int lane = threadIdx.x & 31;
    int m = unit>>4, h = unit&15;
    const float* v = g_proj + ((size_t)m*5+1)*Edim + h*64;
    const float* r = g_proj + ((size_t)m*5+2)*Edim + h*64;
    float s = v[lane]*r[lane] + v[lane+32]*r[lane+32];
    #pragma unroll
    for (int o=16;o;o>>=1) s += __shfl_xor_sync(0xffffffffu, s, o);
    if (lane==0) g_vr[unit] = s;
}

// K7: WKV recurrence, chunked CH=16.
__global__ __launch_bounds__(256) void k_recur(){
    int unit = blockIdx.x;
    int b = unit >> 4, h = unit & 15;
    int tid = threadIdx.x;
    int row = tid >> 2, q = tid & 3, c0 = q*16;
    __shared__ float sk[CH][64], su[CH][64], sw[CH][64], sv[CH][64], sr[CH][64];
    __shared__ float svr[CH], sout[CH][64];
    float S[16];
    #pragma unroll
    for (int j=0;j<16;j++) S[j] = 0.f;
    int mbase = b*Tdim;
    float rk[4], ru[4], rw[4], rv[4], rr[4], rvr = 0.f;

    #pragma unroll
    for (int it=0;it<4;it++){
        int idx = tid + it*256; int st = idx>>6, col = idx&63;
        size_t m = (size_t)(mbase + st);
        const float* bp = g_proj + m*5*Edim + h*64 + col;
        rk[it] = bp[0]; rv[it] = bp[Edim]; rr[it] = bp[2*Edim]; ru[it] = bp[4*Edim];
        rw[it] = g_wdec[m*Edim + h*64 + col];
    }
    if (tid < CH) rvr = g_vr[(mbase+tid)*Hdim + h];

    for (int c=0; c<Tdim/CH; c++){
        #pragma unroll
        for (int it=0;it<4;it++){
            int idx = tid + it*256; int st = idx>>6, col = idx&63;
            sk[st][col]=rk[it]; su[st][col]=ru[it]; sw[st][col]=rw[it];
            sv[st][col]=rv[it]; sr[st][col]=rr[it];
        }
        if (tid < CH) svr[tid] = rvr;
        __syncthreads();
        if (c+1 < Tdim/CH){
            int t0 = (c+1)*CH;
            #pragma unroll
            for (int it=0;it<4;it++){
                int idx = tid + it*256; int st = idx>>6, col = idx&63;
                size_t m = (size_t)(mbase + t0 + st);
                const float* bp = g_proj + m*5*Edim + h*64 + col;
                rk[it] = bp[0]; rv[it] = bp[Edim]; rr[it] = bp[2*Edim]; ru[it] = bp[4*Edim];
                rw[it] = g_wdec[m*Edim + h*64 + col];
            }
            if (tid < CH) rvr = g_vr[(mbase+t0+tid)*Hdim + h];
        }
        #pragma unroll
        for (int t=0;t<CH;t++){
            float kc = sk[t][row], wc = sw[t][row], uc = su[t][row], vc = svr[t];
            const float4* rv4 = (const float4*)&sr[t][c0];
            const float4* vv4 = (const float4*)&sv[t][c0];
            float d0=0.f,d1=0.f,d2=0.f,d3=0.f;
            #pragma unroll
            for (int jj=0;jj<4;jj++){
                float4 rrx = rv4[jj];
                d0 += S[jj*4+0]*rrx.x; d1 += S[jj*4+1]*rrx.y;
                d2 += S[jj*4+2]*rrx.z; d3 += S[jj*4+3]*rrx.w;
            }
            float dot = (d0+d1)+(d2+d3);
            dot += __shfl_xor_sync(0xffffffffu, dot, 1);
            dot += __shfl_xor_sync(0xffffffffu, dot, 2);
            if (q==0) sout[t][row] = uc*kc*vc + dot;
            #pragma unroll
            for (int jj=0;jj<4;jj++){
                float4 vv = vv4[jj];
                S[jj*4+0] = kc*vv.x + wc*S[jj*4+0];
                S[jj*4+1] = kc*vv.y + wc*S[jj*4+1];
                S[jj*4+2] = kc*vv.z + wc*S[jj*4+2];
                S[jj*4+3] = kc*vv.w + wc*S[jj*4+3];
            }
        }
        __syncthreads();
        #pragma unroll
        for (int it=0;it<4;it++){
            int idx = tid + it*256; int st = idx>>6, col = idx&63;
            g_rwkv[(size_t)(mbase + c*CH + st)*Edim + h*64 + col] = sout[st][col];
        }
    }
}

// K8: GroupNorm(16 groups, eps=1e-3) * silu(gate)
__global__ __launch_bounds__(256) void k_gn(const float* __restrict__ gamma,
                                            const float* __restrict__ beta){
    int unit = blockIdx.x*8 + (threadIdx.x>>5);
    int lane = threadIdx.x & 31;
    int m = unit>>4, h = unit&15;
    size_t base = (size_t)m*Edim + h*64;
    float v1 = g_rwkv[base + lane];
    float v2 = g_rwkv[base + 32 + lane];
    float s = v1+v2, sq = v1*v1 + v2*v2;
    #pragma unroll
    for (int o=16;o;o>>=1){
        s  += __shfl_xor_sync(0xffffffffu, s, o);
        sq += __shfl_xor_sync(0xffffffffu, sq, o);
    }
    float mean = s*(1.f/64.f);
    float var  = sq*(1.f/64.f) - mean*mean;
    float rstd = rsqrtf(var + 1e-3f);
    #pragma unroll
    for (int half=0; half<2; half++){
        int e = h*64 + half*32 + lane;
        float v = half ? v2 : v1;
        float nv = (v-mean)*rstd*gamma[e] + beta[e];
        float gg = g_gate[(size_t)m*Edim + e];
        g_a[(size_t)m*Edim + e] = nv * (gg/(1.f+expf(-gg)));
    }
}

extern "C" void kernel_launch(void* const* d_in, const int* in_sizes, int n_in,
                              void* d_out, int out_size) {
    const float* x    = (const float*)d_in[0];
    const float* mu_x = (const float*)d_in[1];
    const float* lam  = (const float*)d_in[2];
    const float* Aw   = (const float*)d_in[3];
    const float* Ab   = (const float*)d_in[4];
    const float* Bw   = (const float*)d_in[5];
    const float* Bb   = (const float*)d_in[6];
    const float* mhd  = (const float*)d_in[7];
    const float* gw   = (const float*)d_in[8];
    const float* wlam = (const float*)d_in[9];
    const float* wA   = (const float*)d_in[10];
    const float* wB   = (const float*)d_in[11];
    const float* gng  = (const float*)d_in[12];
    const float* gnb  = (const float*)d_in[13];
    const float* ow   = (const float*)d_in[14];
    const float* ob   = (const float*)d_in[15];
    float* out = (float*)d_out;

    float *p_dd, *p_gate, *p_a;
    cudaGetSymbolAddress((void**)&p_dd,   g_dd);
    cudaGetSymbolAddress((void**)&p_gate, g_gate);
    cudaGetSymbolAddress((void**)&p_a,    g_a);
    float *p_proj;
    cudaGetSymbolAddress((void**)&p_proj, g_proj);

    k_shift<<<(Mdim*Edim)/256, 256>>>(x, mu_x);
    k_loraA<<<dim3(Mdim/64, 6), 256>>>(Aw, Ab);
    k_loraB<<<dim3(Edim/256, Mdim/16, 6), 256>>>(x, Bw, lam, Bb);
    k_headgemm<<<dim3(Mdim/64, 80), 256>>>(p_dd, 6*Edim, mhd, p_proj, 5*Edim);
    k_gemm<<<dim3(Mdim/128, Edim/128), 256>>>(p_dd + 5*Edim, 6*Edim, gw, nullptr, p_gate, Edim);
    k_wdecay<<<dim3(Mdim/64, 16), 256>>>(wlam, wA, wB);
    k_vr<<<(Mdim*Hdim)/8, 256>>>();
    k_recur<<<Bdim*Hdim, 256>>>();
    k_gn<<<(Mdim*Hdim)/8, 256>>>(gng, gnb);
    k_gemm<<<dim3(Mdim/128, Edim/128), 256>>>(p_a, Edim, ow, ob, out, Edim);
}

// round 8
// speedup vs baseline: 1.3931x; 1.3931x over previous
#include <cuda_runtime.h>
#include <cuda_bf16.h>
#include <cstdint>

#define Bdim 2
#define Tdim 1024
#define Edim 1024
#define Hdim 16
#define Ddim 64
#define Rdim 32
#define Mdim (Bdim*Tdim)
#define CH 16

typedef unsigned long long ull;

// ---------------- scratch ----------------
__device__ float g_hdn [(size_t)Mdim*6*Rdim];
__device__ float g_dd  [(size_t)Mdim*6*Edim];
__device__ float g_proj[(size_t)Mdim*5*Edim];
__device__ float g_gate[(size_t)Mdim*Edim];
__device__ float g_wdec[(size_t)Mdim*Edim];
__device__ float g_vr  [(size_t)Mdim*Hdim];
__device__ float g_rwkv[(size_t)Mdim*Edim];
__device__ __align__(16) __nv_bfloat16 g_gah[(size_t)Mdim*Edim];
__device__ __align__(16) __nv_bfloat16 g_gal[(size_t)Mdim*Edim];
__device__ __align__(16) __nv_bfloat16 g_oah[(size_t)Mdim*Edim];
__device__ __align__(16) __nv_bfloat16 g_oal[(size_t)Mdim*Edim];
__device__ __align__(16) __nv_bfloat16 g_gwt_h[(size_t)Edim*Edim];
__device__ __align__(16) __nv_bfloat16 g_gwt_l[(size_t)Edim*Edim];
__device__ __align__(16) __nv_bfloat16 g_owt_h[(size_t)Edim*Edim];
__device__ __align__(16) __nv_bfloat16 g_owt_l[(size_t)Edim*Edim];

// ---------------- f32x2 helpers (head gemms) ----------------
__device__ __forceinline__ ull pack2(float lo, float hi){
    ull r; asm("mov.b64 %0, {%1, %2};" : "=l"(r) : "f"(lo), "f"(hi)); return r;
}
__device__ __forceinline__ void fma2(ull& d, ull a, ull b){
    asm("fma.rn.f32x2 %0, %1, %2, %3;" : "=l"(d) : "l"(a), "l"(b), "l"(d));
}
__device__ __forceinline__ float2 unpack2(ull v){
    float lo, hi; asm("mov.b64 {%0, %1}, %2;" : "=f"(lo), "=f"(hi) : "l"(v));
    return make_float2(lo, hi);
}

__device__ __forceinline__ uint32_t smem_u32(const void* p){
    uint32_t a; asm("{ .reg .u64 t; cvta.to.shared.u64 t, %1; cvt.u32.u64 %0, t; }" : "=r"(a) : "l"(p));
    return a;
}
#define SW128(o) ((o) ^ ((((uint32_t)(o))>>3) & 0x70u))

#define LDSM4(r, addr) \
    asm volatile("ldmatrix.sync.aligned.m8n8.x4.shared.b16 {%0,%1,%2,%3}, [%4];" \
        : "=r"((r)[0]), "=r"((r)[1]), "=r"((r)[2]), "=r"((r)[3]) : "r"(addr))

#define MMA_BF16(c, a, b0, b1) \
    asm volatile("mma.sync.aligned.m16n8k16.row.col.f32.bf16.bf16.f32 " \
        "{%0,%1,%2,%3}, {%4,%5,%6,%7}, {%8,%9}, {%0,%1,%2,%3};" \
        : "+f"((c)[0]), "+f"((c)[1]), "+f"((c)[2]), "+f"((c)[3]) \
        : "r"((a)[0]), "r"((a)[1]), "r"((a)[2]), "r"((a)[3]), "r"(b0), "r"(b1))

// ---------------- K0: transpose + bf16-split weights (scalar smem ops; [32][33] is
// conflict-free for scalars but 132B rows are NOT float4-aligned) ----------------
__global__ __launch_bounds__(256) void k_wprep(const float* __restrict__ gw,
                                               const float* __restrict__ ow){
    __shared__ float tile[32][33];
    const float* src = blockIdx.z ? ow : gw;
    __nv_bfloat16* dh = blockIdx.z ? g_owt_h : g_gwt_h;
    __nv_bfloat16* dl = blockIdx.z ? g_owt_l : g_gwt_l;
    int k0 = blockIdx.x*32, n0 = blockIdx.y*32;
    int tid = threadIdx.x;
    int r = tid>>3, c = (tid&7)*4;
    float4 v4 = *(const float4*)&src[(size_t)(k0+r)*Edim + n0 + c];
    tile[r][c+0] = v4.x; tile[r][c+1] = v4.y;
    tile[r][c+2] = v4.z; tile[r][c+3] = v4.w;
    __syncthreads();
    #pragma unroll
    for (int j=0;j<4;j++){
        float v = tile[c+j][r];
        __nv_bfloat16 hi = __float2bfloat16(v);
        __nv_bfloat16 lo = __float2bfloat16(v - __bfloat162float(hi));
        size_t di = (size_t)(n0+r)*Edim + k0 + c + j;
        dh[di] = hi; dl[di] = lo;
    }
}

// ---------------- K1: hdn = tanh(z @ Aw[g] + Ab[g]), z inline ----------------
__global__ __launch_bounds__(256) void k_loraA(const float* __restrict__ x,
                                               const float* __restrict__ mu_x,
                                               const float* __restrict__ Aw,
                                               const float* __restrict__ Ab){
    __shared__ float zsm[64][36];
    __shared__ float wsm[32][32];
    int g  = blockIdx.y;
    int m0 = blockIdx.x*64;
    int tid = threadIdx.x;
    int n = tid & 31, ty = tid >> 5;
    float acc[8];
    #pragma unroll
    for (int i=0;i<8;i++) acc[i]=0.f;
    const float* wbase = Aw + (size_t)g*Edim*Rdim;
    for (int k0=0;k0<Edim;k0+=32){
        #pragma unroll
        for (int j=0;j<2;j++){
            int f = tid + j*256;
            int row = f>>3, c4 = (f&7)*4;
            int m = m0 + row;
            float4 xv = *(const float4*)&x[(size_t)m*Edim + k0 + c4];
            float4 lx = make_float4(0.f,0.f,0.f,0.f);
            if (m & (Tdim-1)) lx = *(const float4*)&x[(size_t)(m-1)*Edim + k0 + c4];
            float4 mu = *(const float4*)&mu_x[k0 + c4];
            float4 z;
            { float d=lx.x-xv.x; z.x = xv.x + d*(xv.x + d*mu.x); }
            { float d=lx.y-xv.y; z.y = xv.y + d*(xv.y + d*mu.y); }
            { float d=lx.z-xv.z; z.z = xv.z + d*(xv.z + d*mu.z); }
            { float d=lx.w-xv.w; z.w = xv.w + d*(xv.w + d*mu.w); }
            *(float4*)&zsm[row][c4] = z;
        }
        {
            int kk = tid>>3, c4 = (tid&7)*4;
            *(float4*)&wsm[kk][c4] = *(const float4*)&wbase[(size_t)(k0+kk)*Rdim + c4];
        }
        __syncthreads();
        #pragma unroll
        for (int kk=0;kk<32;kk++){
            float bw = wsm[kk][n];
            #pragma unroll
            for (int i=0;i<8;i++) acc[i] += zsm[ty*8+i][kk]*bw;
        }
        __syncthreads();
    }
    float bias = Ab[g*Rdim + n];
    #pragma unroll
    for (int i=0;i<8;i++)
        g_hdn[(size_t)(m0+ty*8+i)*192 + g*32 + n] = tanhf(acc[i] + bias);
}

// ---------------- K2: dd = x + diff*(lam + hdn@Bw + Bb); g==5 emits bf16 hi/lo ----------------
__global__ __launch_bounds__(256) void k_loraB(const float* __restrict__ x,
                                               const float* __restrict__ Bw,
                                               const float* __restrict__ lam,
                                               const float* __restrict__ Bb){
    __shared__ float hsm[16][32];
    int g  = blockIdx.z;
    int m0 = blockIdx.y*16;
    int tid = threadIdx.x;
    int e  = blockIdx.x*256 + tid;
    float wreg[32];
    const float* wb = Bw + (size_t)g*Rdim*Edim + e;
    #pragma unroll
    for (int r=0;r<32;r++) wreg[r] = wb[(size_t)r*Edim];
    {
        int f = tid;     hsm[f>>5][f&31] = g_hdn[(size_t)(m0+(f>>5))*192 + g*32 + (f&31)];
        f = tid + 256;   hsm[f>>5][f&31] = g_hdn[(size_t)(m0+(f>>5))*192 + g*32 + (f&31)];
    }
    __syncthreads();
    float base = lam[g*Edim + e] + Bb[g*Edim + e];
    #pragma unroll
    for (int mm=0;mm<16;mm++){
        float acc = base;
        #pragma unroll
        for (int r=0;r<32;r++) acc += hsm[mm][r]*wreg[r];
        int m = m0 + mm;
        size_t xi = (size_t)m*Edim + e;
        float xv = x[xi];
        float lx = (m & (Tdim-1)) ? x[xi - Edim] : 0.f;
        float ddv = xv + (lx - xv)*acc;
        g_dd[((size_t)m*6 + g)*Edim + e] = ddv;
        if (g == 5){
            __nv_bfloat16 hi = __float2bfloat16(ddv);
            g_gah[xi] = hi;
            g_gal[xi] = __float2bfloat16(ddv - __bfloat162float(hi));
        }
    }
}

// ---------------- K3: per-head 64x64 GEMM (proj) ----------------
__global__ __launch_bounds__(256) void k_headgemm(const float* __restrict__ in, int in_rstride,
                                                  const float* __restrict__ w,
                                                  float* __restrict__ out, int out_rstride){
    __shared__ float ysm[64][68];
    __shared__ float wsm[64][64];
    int unit = blockIdx.y;
    int m0   = blockIdx.x*64;
    int colbase = (unit>>4)*Edim + (unit&15)*64;
    const float* wb = w + (size_t)unit*4096;
    int tid = threadIdx.x;
    #pragma unroll
    for (int j=0;j<4;j++){
        int f = tid + j*256;
        int row = f>>4, c4 = (f&15)*4;
        *(float4*)&ysm[row][c4] = *(const float4*)&in[(size_t)(m0+row)*in_rstride + colbase + c4];
        *(float4*)&wsm[row][c4] = *(const float4*)&wb[row*64 + c4];
    }
    __syncthreads();
    int tx = tid&15, ty = tid>>4;
    int n0 = tx*4, m0r = ty*4;
    ull acc[4][2];
    #pragma unroll
    for (int i=0;i<4;i++){ acc[i][0]=0ull; acc[i][1]=0ull; }
    #pragma unroll 16
    for (int k=0;k<64;k++){
        ull b01 = *(const ull*)&wsm[k][n0];
        ull b23 = *(const ull*)&wsm[k][n0+2];
        #pragma unroll
        for (int i=0;i<4;i++){
            float a = ysm[m0r+i][k];
            ull a2 = pack2(a, a);
            fma2(acc[i][0], a2, b01);
            fma2(acc[i][1], a2, b23);
        }
    }
    #pragma unroll
    for (int i=0;i<4;i++){
        float2 lo = unpack2(acc[i][0]), hi = unpack2(acc[i][1]);
        *(float4*)&out[(size_t)(m0+m0r+i)*out_rstride + colbase + n0] =
            make_float4(lo.x, lo.y, hi.x, hi.y);
    }
}

// ---------------- K3b: fused decay lora ----------------
__global__ __launch_bounds__(256) void k_wdecay(const float* __restrict__ wlam,
                                                const float* __restrict__ wA,
                                                const float* __restrict__ wB){
    __shared__ float asm_[64][68];
    __shared__ float wsm[64][68];
    int h = blockIdx.y;
    int m0 = blockIdx.x*64;
    int tid = threadIdx.x;
    #pragma unroll
    for (int j=0;j<4;j++){
        int f = tid + j*256;
        int row = f>>4, c4 = (f&15)*4;
        *(float4*)&asm_[row][c4] =
            *(const float4*)&g_proj[(size_t)(m0+row)*5*Edim + 3*Edim + h*64 + c4];
        *(float4*)&wsm[row][c4] = *(const float4*)&wA[(size_t)h*4096 + row*64 + c4];
    }
    __syncthreads();
    int tx = tid&15, ty = tid>>4;
    int n0 = tx*4, m0r = ty*4;
    ull acc[4][2];
    #pragma unroll
    for (int i=0;i<4;i++){ acc[i][0]=0ull; acc[i][1]=0ull; }
    #pragma unroll 16
    for (int k=0;k<64;k++){
        ull b01 = *(const ull*)&wsm[k][n0];
        ull b23 = *(const ull*)&wsm[k][n0+2];
        #pragma unroll
        for (int i=0;i<4;i++){
            float a = asm_[m0r+i][k];
            ull a2 = pack2(a, a);
            fma2(acc[i][0], a2, b01);
            fma2(acc[i][1], a2, b23);
        }
    }
    __syncthreads();
    #pragma unroll
    for (int i=0;i<4;i++){
        float2 lo = unpack2(acc[i][0]), hi = unpack2(acc[i][1]);
        *(float4*)&asm_[m0r+i][n0] =
            make_float4(tanhf(lo.x), tanhf(lo.y), tanhf(hi.x), tanhf(hi.y));
        acc[i][0]=0ull; acc[i][1]=0ull;
    }
    #pragma unroll
    for (int j=0;j<4;j++){
        int f = tid + j*256;
        int row = f>>4, c4 = (f&15)*4;
        *(float4*)&wsm[row][c4] = *(const float4*)&wB[(size_t)h*4096 + row*64 + c4];
    }
    __syncthreads();
    #pragma unroll 16
    for (int k=0;k<64;k++){
        ull b01 = *(const ull*)&wsm[k][n0];
        ull b23 = *(const ull*)&wsm[k][n0+2];
        #pragma unroll
        for (int i=0;i<4;i++){
            float a = asm_[m0r+i][k];
            ull a2 = pack2(a, a);
            fma2(acc[i][0], a2, b01);
            fma2(acc[i][1], a2, b23);
        }
    }
    #pragma unroll
    for (int i=0;i<4;i++){
        float2 lo = unpack2(acc[i][0]), hi = unpack2(acc[i][1]);
        float v[4] = {lo.x, lo.y, hi.x, hi.y};
        #pragma unroll
        for (int j=0;j<4;j++)
            v[j] = expf(-expf(v[j] + wlam[h*64 + n0 + j]));
        *(float4*)&g_wdec[(size_t)(m0+m0r+i)*Edim + h*64 + n0] =
            make_float4(v[0],v[1],v[2],v[3]);
    }
}

// ---------------- K4: HMMA bf16-split GEMM  C[2048,1024] = A @ Wt^T (+bias) ----------------
#define HS_BUF 16384
#define HS_SMEM (4*HS_BUF + 1024)
__global__ __launch_bounds__(256)
void k_gemm_hmma(const __nv_bfloat16* __restrict__ Ah, const __nv_bfloat16* __restrict__ Al,
                 const __nv_bfloat16* __restrict__ Bh, const __nv_bfloat16* __restrict__ Bl,
                 const float* __restrict__ bias, float* __restrict__ C){
    extern __shared__ char smg[];
    uint32_t dynb = smem_u32(smg);
    uint32_t db = (dynb + 1023u) & ~1023u;
    char* dptr = smg + (db - dynb);
    int tid = threadIdx.x, wid = tid>>5, lane = tid&31;
    int mBase = blockIdx.x*128, nBase = blockIdx.y*128;
    int wm = (wid&1)*64, wn = (wid>>1)*32;

    uint32_t sAh = db, sAl = db + HS_BUF, sBh = db + 2*HS_BUF, sBl = db + 3*HS_BUF;

    float acc[4][4][4];
    #pragma unroll
    for (int mt=0;mt<4;mt++)
        #pragma unroll
        for (int nt=0;nt<4;nt++)
            #pragma unroll
            for (int j=0;j<4;j++) acc[mt][nt][j]=0.f;

    int lrow = tid>>3, lc = tid&7;
    uint4 pa[4], pal[4], pb[4], pbl[4];
    #pragma unroll
    for (int jj=0;jj<4;jj++){
        int row = lrow + jj*32;
        pa[jj]  = *(const uint4*)&Ah[(size_t)(mBase+row)*Edim + lc*8];
        pal[jj] = *(const uint4*)&Al[(size_t)(mBase+row)*Edim + lc*8];
        pb[jj]  = *(const uint4*)&Bh[(size_t)(nBase+row)*Edim + lc*8];
        pbl[jj] = *(const uint4*)&Bl[(size_t)(nBase+row)*Edim + lc*8];
    }
    for (int i=0;i<16;i++){
        uint32_t swo[4];
        #pragma unroll
        for (int jj=0;jj<4;jj++){
            int row = lrow + jj*32;
            swo[jj] = SW128((uint32_t)(row*128 + lc*16));
            *(uint4*)(dptr + swo[jj])            = pa[jj];
            *(uint4*)(dptr + HS_BUF + swo[jj])   = pal[jj];
            *(uint4*)(dptr + 2*HS_BUF + swo[jj]) = pb[jj];
            *(uint4*)(dptr + 3*HS_BUF + swo[jj]) = pbl[jj];
        }
        __syncthreads();
        if (i+1 < 16){
            int k0 = (i+1)*64;
            #pragma unroll
            for (int jj=0;jj<4;jj++){
                int row = lrow + jj*32;
                pa[jj]  = *(const uint4*)&Ah[(size_t)(mBase+row)*Edim + k0 + lc*8];
                pal[jj] = *(const uint4*)&Al[(size_t)(mBase+row)*Edim + k0 + lc*8];
                pb[jj]  = *(const uint4*)&Bh[(size_t)(nBase+row)*Edim + k0 + lc*8];
                pbl[jj] = *(const uint4*)&Bl[(size_t)(nBase+row)*Edim + k0 + lc*8];
            }
        }
        #pragma unroll
        for (int ks=0;ks<4;ks++){
            uint32_t ah[4][4], al[4][4];
            #pragma unroll
            for (int mt=0;mt<4;mt++){
                uint32_t off = SW128((uint32_t)((wm+mt*16+(lane&15))*128 + ks*32 + (lane>>4)*16));
                LDSM4(ah[mt], sAh + off);
                LDSM4(al[mt], sAl + off);
            }
            uint32_t bh[2][4], bl[2][4];
            #pragma unroll
            for (int p=0;p<2;p++){
                int brow = wn + p*16 + ((lane>>4)&1)*8 + (lane&7);
                uint32_t off = SW128((uint32_t)(brow*128 + ks*32 + ((lane>>3)&1)*16));
                LDSM4(bh[p], sBh + off);
                LDSM4(bl[p], sBl + off);
            }
            #pragma unroll
            for (int mt=0;mt<4;mt++){
                #pragma unroll
                for (int nt=0;nt<4;nt++){
                    int p = nt>>1, o = (nt&1)*2;
                    MMA_BF16(acc[mt][nt], ah[mt], bh[p][o], bh[p][o+1]);
                    MMA_BF16(acc[mt][nt], ah[mt], bl[p][o], bl[p][o+1]);
                    MMA_BF16(acc[mt][nt], al[mt], bh[p][o], bh[p][o+1]);
                }
            }
        }
        __syncthreads();
    }
    int gr = lane>>2, gc = (lane&3)*2;
    #pragma unroll
    for (int mt=0;mt<4;mt++){
        #pragma unroll
        for (int nt=0;nt<4;nt++){
            int row = mBase + wm + mt*16 + gr;
            int col = nBase + wn + nt*8 + gc;
            float b0 = bias ? bias[col] : 0.f;
            float b1 = bias ? bias[col+1] : 0.f;
            *(float2*)&C[(size_t)row*Edim + col] =
                make_float2(acc[mt][nt][0] + b0, acc[mt][nt][1] + b1);
            *(float2*)&C[(size_t)(row+8)*Edim + col] =
                make_float2(acc[mt][nt][2] + b0, acc[mt][nt][3] + b1);
        }
    }
}

// ---------------- K5: vr[m,h] = dot(v,r) ----------------
__global__ __launch_bounds__(256) void k_vr(){
    int unit = blockIdx.x*8 + (threadIdx.x>>5);
    int lane = threadIdx.x & 31;
    int m = unit>>4, h = unit&15;
    const float* v = g_proj + ((size_t)m*5+1)*Edim + h*64;
    const float* r = g_proj + ((size_t)m*5+2)*Edim + h*64;
    float s = v[lane]*r[lane] + v[lane+32]*r[lane+32];
    #pragma unroll
    for (int o=16;o;o>>=1) s += __shfl_xor_sync(0xffffffffu, s, o);
    if (lane==0) g_vr[unit] = s;
}

// ---------------- K6: WKV recurrence, chunked CH=16 ----------------
__global__ __launch_bounds__(256) void k_recur(){
    int unit = blockIdx.x;
    int b = unit >> 4, h = unit & 15;
    int tid = threadIdx.x;
    int row = tid >> 2, q = tid & 3, c0 = q*16;
    __shared__ float sk[CH][64], su[CH][64], sw[CH][64], sv[CH][64], sr[CH][64];
    __shared__ float svr[CH], sout[CH][64];
    float S[16];
    #pragma unroll
    for (int j=0;j<16;j++) S[j] = 0.f;
    int mbase = b*Tdim;
    float rk[4], ru[4], rw[4], rv[4], rr[4], rvr = 0.f;

    #pragma unroll
    for (int it=0;it<4;it++){
        int idx = tid + it*256; int st = idx>>6, col = idx&63;
        size_t m = (size_t)(mbase + st);
        const float* bp = g_proj + m*5*Edim + h*64 + col;
        rk[it] = bp[0]; rv[it] = bp[Edim]; rr[it] = bp[2*Edim]; ru[it] = bp[4*Edim];
        rw[it] = g_wdec[m*Edim + h*64 + col];
    }
    if (tid < CH) rvr = g_vr[(mbase+tid)*Hdim + h];

    for (int c=0; c<Tdim/CH; c++){
        #pragma unroll
        for (int it=0;it<4;it++){
            int idx = tid + it*256; int st = idx>>6, col = idx&63;
            sk[st][col]=rk[it]; su[st][col]=ru[it]; sw[st][col]=rw[it];
            sv[st][col]=rv[it]; sr[st][col]=rr[it];
        }
        if (tid < CH) svr[tid] = rvr;
        __syncthreads();
        if (c+1 < Tdim/CH){
            int t0 = (c+1)*CH;
            #pragma unroll
            for (int it=0;it<4;it++){
                int idx = tid + it*256; int st = idx>>6, col = idx&63;
                size_t m = (size_t)(mbase + t0 + st);
                const float* bp = g_proj + m*5*Edim + h*64 + col;
                rk[it] = bp[0]; rv[it] = bp[Edim]; rr[it] = bp[2*Edim]; ru[it] = bp[4*Edim];
                rw[it] = g_wdec[m*Edim + h*64 + col];
            }
            if (tid < CH) rvr = g_vr[(mbase+t0+tid)*Hdim + h];
        }
        #pragma unroll
        for (int t=0;t<CH;t++){
            float kc = sk[t][row], wc = sw[t][row], uc = su[t][row], vc = svr[t];
            const float4* rv4 = (const float4*)&sr[t][c0];
            const float4* vv4 = (const float4*)&sv[t][c0];
            float d0=0.f,d1=0.f,d2=0.f,d3=0.f;
            #pragma unroll
            for (int jj=0;jj<4;jj++){
                float4 rrx = rv4[jj];
                d0 += S[jj*4+0]*rrx.x; d1 += S[jj*4+1]*rrx.y;
                d2 += S[jj*4+2]*rrx.z; d3 += S[jj*4+3]*rrx.w;
            }
            float dot = (d0+d1)+(d2+d3);
            dot += __shfl_xor_sync(0xffffffffu, dot, 1);
            dot += __shfl_xor_sync(0xffffffffu, dot, 2);
            if (q==0) sout[t][row] = uc*kc*vc + dot;
            #pragma unroll
            for (int jj=0;jj<4;jj++){
                float4 vv = vv4[jj];
                S[jj*4+0] = kc*vv.x + wc*S[jj*4+0];
                S[jj*4+1] = kc*vv.y + wc*S[jj*4+1];
                S[jj*4+2] = kc*vv.z + wc*S[jj*4+2];
                S[jj*4+3] = kc*vv.w + wc*S[jj*4+3];
            }
        }
        __syncthreads();
        #pragma unroll
        for (int it=0;it<4;it++){
            int idx = tid + it*256; int st = idx>>6, col = idx&63;
            g_rwkv[(size_t)(mbase + c*CH + st)*Edim + h*64 + col] = sout[st][col];
        }
    }
}

// ---------------- K7: GroupNorm * silu(gate) -> bf16 hi/lo ----------------
__global__ __launch_bounds__(256) void k_gn(const float* __restrict__ gamma,
                                            const float* __restrict__ beta){
    int unit = blockIdx.x*8 + (threadIdx.x>>5);
    int lane = threadIdx.x & 31;
    int m = unit>>4, h = unit&15;
    size_t base = (size_t)m*Edim + h*64;
    float v1 = g_rwkv[base + lane];
    float v2 = g_rwkv[base + 32 + lane];
    float s = v1+v2, sq = v1*v1 + v2*v2;
    #pragma unroll
    for (int o=16;o;o>>=1){
        s  += __shfl_xor_sync(0xffffffffu, s, o);
        sq += __shfl_xor_sync(0xffffffffu, sq, o);
    }
    float mean = s*(1.f/64.f);
    float var  = sq*(1.f/64.f) - mean*mean;
    float rstd = rsqrtf(var + 1e-3f);
    #pragma unroll
    for (int half=0; half<2; half++){
        int e = h*64 + half*32 + lane;
        float v = half ? v2 : v1;
        float nv = (v-mean)*rstd*gamma[e] + beta[e];
        float gg = g_gate[(size_t)m*Edim + e];
        float a = nv * (gg/(1.f+expf(-gg)));
        size_t di = (size_t)m*Edim + e;
        __nv_bfloat16 hi = __float2bfloat16(a);
        g_oah[di] = hi;
        g_oal[di] = __float2bfloat16(a - __bfloat162float(hi));
    }
}

extern "C" void kernel_launch(void* const* d_in, const int* in_sizes, int n_in,
                              void* d_out, int out_size) {
    const float* x    = (const float*)d_in[0];
    const float* mu_x = (const float*)d_in[1];
    const float* lam  = (const float*)d_in[2];
    const float* Aw   = (const float*)d_in[3];
    const float* Ab   = (const float*)d_in[4];
    const float* Bw   = (const float*)d_in[5];
    const float* Bb   = (const float*)d_in[6];
    const float* mhd  = (const float*)d_in[7];
    const float* gw   = (const float*)d_in[8];
    const float* wlam = (const float*)d_in[9];
    const float* wA   = (const float*)d_in[10];
    const float* wB   = (const float*)d_in[11];
    const float* gng  = (const float*)d_in[12];
    const float* gnb  = (const float*)d_in[13];
    const float* ow   = (const float*)d_in[14];
    const float* ob   = (const float*)d_in[15];
    float* out = (float*)d_out;

    float *p_dd, *p_proj, *p_gate;
    cudaGetSymbolAddress((void**)&p_dd,   g_dd);
    cudaGetSymbolAddress((void**)&p_proj, g_proj);
    cudaGetSymbolAddress((void**)&p_gate, g_gate);
    __nv_bfloat16 *p_gah, *p_gal, *p_oah, *p_oal, *p_gwh, *p_gwl, *p_owh, *p_owl;
    cudaGetSymbolAddress((void**)&p_gah, g_gah);
    cudaGetSymbolAddress((void**)&p_gal, g_gal);
    cudaGetSymbolAddress((void**)&p_oah, g_oah);
    cudaGetSymbolAddress((void**)&p_oal, g_oal);
    cudaGetSymbolAddress((void**)&p_gwh, g_gwt_h);
    cudaGetSymbolAddress((void**)&p_gwl, g_gwt_l);
    cudaGetSymbolAddress((void**)&p_owh, g_owt_h);
    cudaGetSymbolAddress((void**)&p_owl, g_owt_l);

    static bool attr_done = false;
    if (!attr_done){
        cudaFuncSetAttribute(k_gemm_hmma, cudaFuncAttributeMaxDynamicSharedMemorySize, HS_SMEM);
        attr_done = true;
    }

    k_wprep<<<dim3(Edim/32, Edim/32, 2), 256>>>(gw, ow);
    k_loraA<<<dim3(Mdim/64, 6), 256>>>(x, mu_x, Aw, Ab);
    k_loraB<<<dim3(Edim/256, Mdim/16, 6), 256>>>(x, Bw, lam, Bb);
    k_headgemm<<<dim3(Mdim/64, 80), 256>>>(p_dd, 6*Edim, mhd, p_proj, 5*Edim);
    k_wdecay<<<dim3(Mdim/64, 16), 256>>>(wlam, wA, wB);
    k_gemm_hmma<<<dim3(Mdim/128, Edim/128), 256, HS_SMEM>>>(p_gah, p_gal, p_gwh, p_gwl, nullptr, p_gate);
    k_vr<<<(Mdim*Hdim)/8, 256>>>();
    k_recur<<<Bdim*Hdim, 256>>>();
    k_gn<<<(Mdim*Hdim)/8, 256>>>(gng, gnb);
    k_gemm_hmma<<<dim3(Mdim/128, Edim/128), 256, HS_SMEM>>>(p_oah, p_oal, p_owh, p_owl, ob, out);
}